// round 2
// baseline (speedup 1.0000x reference)
#include <cuda_runtime.h>

// Spatial GCN on a 24x24 grid graph.
// Key insight: adj = D^-1 A + I for the 4-neighbor grid, so X @ adj is a
// 5-point stencil: support[l] = x[l] + sum_{k~l} x[k]/deg[k].
// Then y = support * weight[c, node]; BatchNorm2d (batch stats) + LeakyReLU(0.2).
//
// Pass 1: stencil + weight, per-(b,c) partial sums for BN stats (deterministic).
// Pass 2: finalize per-channel scale/shift.
// Pass 3: recompute stencil (x is L2-resident), normalize + LeakyReLU, write out.

#define B_   64
#define C_   512
#define Nn   24
#define NN   576            // 24*24
#define BN_EPS 1e-4f
#define SLOPE  0.2f

__device__ float g_psum[C_ * B_];
__device__ float g_psq [C_ * B_];
__device__ float g_scale[C_];
__device__ float g_shift[C_];

__device__ __forceinline__ float invdeg(int i, int j) {
    int d = (i > 0) + (i < Nn - 1) + (j > 0) + (j < Nn - 1);
    // d in {2,3,4}
    return d == 4 ? 0.25f : (d == 3 ? 0.33333334f : 0.5f);
}

__device__ __forceinline__ float stencil_val(const float* __restrict__ xs, int t) {
    int i = t / Nn;
    int j = t - i * Nn;
    float s = xs[t];
    if (j > 0)      s += xs[t - 1]  * invdeg(i, j - 1);
    if (j < Nn - 1) s += xs[t + 1]  * invdeg(i, j + 1);
    if (i > 0)      s += xs[t - Nn] * invdeg(i - 1, j);
    if (i < Nn - 1) s += xs[t + Nn] * invdeg(i + 1, j);
    return s;
}

// ---------------- Pass 1: stats ----------------
__global__ __launch_bounds__(NN) void k_stats(const float* __restrict__ x,
                                              const float* __restrict__ w) {
    int bc = blockIdx.x;          // b*C_ + c
    int b  = bc >> 9;             // / 512
    int c  = bc & (C_ - 1);
    const float* xp = x + (size_t)bc * NN;

    __shared__ float xs[NN];
    int t = threadIdx.x;
    xs[t] = xp[t];
    __syncthreads();

    float s = stencil_val(xs, t);
    float y = s * __ldg(&w[c * NN + t]);

    float s1 = y, s2 = y * y;
    #pragma unroll
    for (int o = 16; o; o >>= 1) {
        s1 += __shfl_down_sync(0xFFFFFFFFu, s1, o);
        s2 += __shfl_down_sync(0xFFFFFFFFu, s2, o);
    }
    __shared__ float ws1[18], ws2[18];
    int wid = t >> 5, lane = t & 31;
    if (lane == 0) { ws1[wid] = s1; ws2[wid] = s2; }
    __syncthreads();
    if (wid == 0) {
        s1 = (lane < 18) ? ws1[lane] : 0.0f;
        s2 = (lane < 18) ? ws2[lane] : 0.0f;
        #pragma unroll
        for (int o = 16; o; o >>= 1) {
            s1 += __shfl_down_sync(0xFFFFFFFFu, s1, o);
            s2 += __shfl_down_sync(0xFFFFFFFFu, s2, o);
        }
        if (lane == 0) {
            g_psum[c * B_ + b] = s1;
            g_psq [c * B_ + b] = s2;
        }
    }
}

// ---------------- Pass 2: finalize per-channel scale/shift ----------------
__global__ void k_finalize(const float* __restrict__ gamma,
                           const float* __restrict__ beta) {
    int c = threadIdx.x;   // 512 threads
    float s1 = 0.0f, s2 = 0.0f;
    #pragma unroll 8
    for (int b = 0; b < B_; b++) {
        s1 += g_psum[c * B_ + b];
        s2 += g_psq [c * B_ + b];
    }
    const float invn = 1.0f / (float)(B_ * NN);  // 1/36864
    float mean = s1 * invn;
    float var  = s2 * invn - mean * mean;
    float sc = gamma[c] * rsqrtf(var + BN_EPS);
    g_scale[c] = sc;
    g_shift[c] = beta[c] - mean * sc;
}

// ---------------- Pass 3: normalize + LeakyReLU ----------------
__global__ __launch_bounds__(NN) void k_out(const float* __restrict__ x,
                                            const float* __restrict__ w,
                                            float* __restrict__ out) {
    int bc = blockIdx.x;
    int c  = bc & (C_ - 1);
    const float* xp = x + (size_t)bc * NN;

    __shared__ float xs[NN];
    int t = threadIdx.x;
    xs[t] = xp[t];
    __syncthreads();

    float s = stencil_val(xs, t);
    float y = s * __ldg(&w[c * NN + t]);

    float yn = y * g_scale[c] + g_shift[c];
    float r  = (yn >= 0.0f) ? yn : SLOPE * yn;
    out[(size_t)bc * NN + t] = r;
}

extern "C" void kernel_launch(void* const* d_in, const int* in_sizes, int n_in,
                              void* d_out, int out_size) {
    const float* x     = (const float*)d_in[0];   // [64,512,24,24]
    // d_in[1] = adj (unused: structure exploited analytically)
    const float* w     = (const float*)d_in[2];   // [512,576]
    const float* gamma = (const float*)d_in[3];   // [512]
    const float* beta  = (const float*)d_in[4];   // [512]
    float* out = (float*)d_out;

    dim3 grid(B_ * C_);       // 32768 blocks, one per (b,c) image
    k_stats<<<grid, NN>>>(x, w);
    k_finalize<<<1, C_>>>(gamma, beta);
    k_out<<<grid, NN>>>(x, w, out);
}

// round 3
// speedup vs baseline: 1.7804x; 1.7804x over previous
#include <cuda_runtime.h>

// Spatial GCN on a 24x24 grid: adj = D^-1 A + I (4-neighbor grid) => 5-point
// stencil with analytic 1/deg in {1/2, 1/3, 1/4}. Then elementwise weight,
// BatchNorm2d (batch stats), LeakyReLU(0.2).
//
// R3: 2 rows (48 elems) per thread, 16 images per 192-thread block, all
// vectorized (float4 LDS/LDG/STG), coefficients hoisted per-row, full unroll.

#define B_   64
#define C_   512
#define Nn   24
#define NN   576
#define G_   16          // images per block
#define T_   192         // threads per block (12 threads/image, 2 rows each)
#define BN_EPS 1e-4f
#define SLOPE  0.2f

__device__ float g_psum[C_ * B_];
__device__ float g_psq [C_ * B_];
__device__ float g_scale[C_];
__device__ float g_shift[C_];

__device__ __forceinline__ float invd(int d) {
    // d in {2,3,4}; (float)(1.0/3.0) == 1.0f/3.0f == 0x3EAAAAAB
    return d == 4 ? 0.25f : (d == 3 ? (1.0f / 3.0f) : 0.5f);
}

__device__ __forceinline__ float f4c(const float4& v, int k) {
    return k == 0 ? v.x : (k == 1 ? v.y : (k == 2 ? v.z : v.w));
}

template <bool STATS>
__global__ __launch_bounds__(T_) void k_main(const float* __restrict__ x,
                                             const float* __restrict__ w,
                                             float* __restrict__ out) {
    __shared__ float xs[G_ * NN];        // 36 KB
    __shared__ float ps1[T_], ps2[T_];

    const int tid = threadIdx.x;
    const int base_bc = blockIdx.x * G_;

    // ---- coalesced stage of 16 images ----
    const float4* x4 = (const float4*)(x + (size_t)base_bc * NN);
    float4* xs4 = (float4*)xs;
    #pragma unroll
    for (int k = 0; k < (G_ * NN / 4) / T_; k++)     // 12 iters
        xs4[tid + k * T_] = x4[tid + k * T_];
    __syncthreads();

    const int g  = tid / 12;
    const int r0 = (tid - g * 12) * 2;
    const int bc = base_bc + g;
    const int c  = bc & (C_ - 1);
    const float* img = xs + g * NN;

    float s1 = 0.0f, s2 = 0.0f;
    float scale = 0.0f, shift = 0.0f;
    if (!STATS) { scale = g_scale[c]; shift = g_shift[c]; }

    #pragma unroll
    for (int rr = 0; rr < 2; rr++) {
        const int i = r0 + rr;
        const float* xr = img + i * Nn;

        const int rt  = (i > 0) + (i < Nn - 1);
        const int rtu = (i > 1) + 1;          // rowterm(i-1), valid iff i>0
        const int rtd = 1 + (i < Nn - 2);     // rowterm(i+1), valid iff i<23
        const float cH_i = invd(rt + 2),  cH_e = invd(rt + 1);
        float cU_i = invd(rtu + 2), cU_e = invd(rtu + 1);
        float cD_i = invd(rtd + 2), cD_e = invd(rtd + 1);
        // zero out missing vertical neighbors; clamp pointers to valid smem
        const float* xu = xr;  const float* xd = xr;
        if (i > 0)      xu = xr - Nn; else { cU_i = 0.0f; cU_e = 0.0f; }
        if (i < Nn - 1) xd = xr + Nn; else { cD_i = 0.0f; cD_e = 0.0f; }

        // center row into registers (6 LDS.128)
        float xc[Nn];
        #pragma unroll
        for (int q = 0; q < 6; q++) {
            float4 t = *(const float4*)(xr + 4 * q);
            xc[4*q] = t.x; xc[4*q+1] = t.y; xc[4*q+2] = t.z; xc[4*q+3] = t.w;
        }

        const float4* wr4 = (const float4*)(w + c * NN + i * Nn);
        float4* o4p = (float4*)(out + (size_t)bc * NN + i * Nn);

        #pragma unroll
        for (int q = 0; q < 6; q++) {
            const float4 wq = __ldg(&wr4[q]);
            const float4 uq = *(const float4*)(xu + 4 * q);
            const float4 dq = *(const float4*)(xd + 4 * q);
            float yy[4];
            #pragma unroll
            for (int jj = 0; jj < 4; jj++) {
                const int j = 4 * q + jj;
                float s = xc[j];
                if (j > 0)      s += ((j == 1)      ? cH_e : cH_i) * xc[j - 1];
                if (j < Nn - 1) s += ((j == Nn - 2) ? cH_e : cH_i) * xc[j + 1];
                const bool edge = (j == 0) || (j == Nn - 1);
                s += (edge ? cU_e : cU_i) * f4c(uq, jj);
                s += (edge ? cD_e : cD_i) * f4c(dq, jj);
                const float y = s * f4c(wq, jj);
                if (STATS) {
                    s1 += y;
                    s2 = fmaf(y, y, s2);
                } else {
                    const float yn = fmaf(y, scale, shift);
                    yy[jj] = (yn >= 0.0f) ? yn : SLOPE * yn;
                }
            }
            if (!STATS)
                o4p[q] = make_float4(yy[0], yy[1], yy[2], yy[3]);
        }
    }

    if (STATS) {
        ps1[tid] = s1; ps2[tid] = s2;
        __syncthreads();
        if (tid < G_) {
            float a = 0.0f, b2 = 0.0f;
            #pragma unroll
            for (int k = 0; k < 12; k++) {
                a  += ps1[tid * 12 + k];
                b2 += ps2[tid * 12 + k];
            }
            const int bc2 = base_bc + tid;
            const int b = bc2 >> 9, cc = bc2 & (C_ - 1);
            g_psum[cc * B_ + b] = a;
            g_psq [cc * B_ + b] = b2;
        }
    }
}

__global__ void k_finalize(const float* __restrict__ gamma,
                           const float* __restrict__ beta) {
    const int c = threadIdx.x;   // 512 threads
    float s1 = 0.0f, s2 = 0.0f;
    #pragma unroll 8
    for (int b = 0; b < B_; b++) {
        s1 += g_psum[c * B_ + b];
        s2 += g_psq [c * B_ + b];
    }
    const float invn = 1.0f / (float)(B_ * NN);
    const float mean = s1 * invn;
    const float var  = s2 * invn - mean * mean;
    const float sc = gamma[c] * rsqrtf(var + BN_EPS);
    g_scale[c] = sc;
    g_shift[c] = beta[c] - mean * sc;
}

extern "C" void kernel_launch(void* const* d_in, const int* in_sizes, int n_in,
                              void* d_out, int out_size) {
    const float* x     = (const float*)d_in[0];   // [64,512,24,24]
    // d_in[1] = adj (unused: grid structure exploited analytically)
    const float* w     = (const float*)d_in[2];   // [512,576]
    const float* gamma = (const float*)d_in[3];   // [512]
    const float* beta  = (const float*)d_in[4];   // [512]
    float* out = (float*)d_out;

    const int nblk = (B_ * C_) / G_;              // 2048
    k_main<true ><<<nblk, T_>>>(x, w, out);
    k_finalize<<<1, C_>>>(gamma, beta);
    k_main<false><<<nblk, T_>>>(x, w, out);
}

// round 4
// speedup vs baseline: 2.8681x; 1.6109x over previous
#include <cuda_runtime.h>

// Spatial GCN on a 24x24 grid: adj = D^-1 A + I (4-neighbor grid) => 5-point
// stencil with analytic 1/deg(neighbor) in {1/2, 1/3, 1/4}. Then elementwise
// weight, BatchNorm2d (batch stats), LeakyReLU(0.2).
//
// R4: chunk-linear mapping. Thread = one float4 chunk; warp lanes cover
// consecutive chunks => all LDG/STG perfectly coalesced. No smem staging;
// neighbors via direct LDG (L1/L2-hit). Branch-free coefficient selection.

#define B_   64
#define C_   512
#define NN   576
#define BN_EPS 1e-4f
#define SLOPE  0.2f

#define TPB  288     // 2 images per block (144 chunks each)

__device__ float g_psum[C_ * B_];
__device__ float g_psq [C_ * B_];
__device__ float g_scale[C_];
__device__ float g_shift[C_];

__device__ __forceinline__ float invd(int d) {
    // d in {2,3,4}
    return d == 4 ? 0.25f : (d == 3 ? (1.0f / 3.0f) : 0.5f);
}

template <bool STATS>
__global__ __launch_bounds__(TPB) void k_main(const float* __restrict__ x,
                                              const float* __restrict__ w,
                                              float* __restrict__ out) {
    __shared__ float ps1[TPB], ps2[TPB];
    __shared__ float qs1[32], qs2[32];

    const int tid = threadIdx.x;
    const int in1 = tid >= 144;                 // which of the 2 images
    const int g   = blockIdx.x * 2 + in1;       // bc index
    const int r   = tid - 144 * in1;            // chunk within image, 0..143
    const int i   = r / 6;                      // row 0..23
    const int q   = r - 6 * i;                  // float4 chunk in row, 0..5
    const int c   = g & (C_ - 1);
    const size_t off = (size_t)g * NN + r * 4;

    // ---- loads (all warp-contiguous) ----
    const float4 ct = *(const float4*)(x + off);
    float4 up = make_float4(0.f, 0.f, 0.f, 0.f);
    float4 dn = make_float4(0.f, 0.f, 0.f, 0.f);
    if (i > 0)  up = *(const float4*)(x + off - 24);
    if (i < 23) dn = *(const float4*)(x + off + 24);
    const float lf = (q > 0) ? __ldg(x + off - 1) : 0.0f;
    const float rg = (q < 5) ? __ldg(x + off + 4) : 0.0f;
    const float4 wv = __ldg((const float4*)(w + c * NN + r * 4));

    // ---- stencil coefficients (1/deg of the NEIGHBOR) ----
    const int rti = (i > 0) + (i < 23);         // rowterm(i)
    const int rtu = (i > 1) + 1;                // rowterm(i-1), valid iff i>0
    const int rtd = 1 + (i < 22);               // rowterm(i+1), valid iff i<23
    const float cHi = invd(rti + 2);            // horiz neighbor, interior col
    const float cHe = invd(rti + 1);            // horiz neighbor at col 0/23
    const float cUi = invd(rtu + 2), cUe = invd(rtu + 1);
    const float cDi = invd(rtd + 2), cDe = invd(rtd + 1);

    const bool q0 = (q == 0), q5 = (q == 5);
    // left coeffs per lane k (neighbor col = 4q+k-1)
    const float cL0 = q0 ? 0.0f : cHi;
    const float cL1 = q0 ? cHe  : cHi;          // neighbor col 0 when q==0
    // right coeffs (neighbor col = 4q+k+1)
    const float cR2 = q5 ? cHe  : cHi;          // neighbor col 23 when q==5
    const float cR3 = q5 ? 0.0f : cHi;
    // vertical coeffs: colterm(j)=1 only at j==0 (q0,k0) / j==23 (q5,k3)
    const float vU = (i > 0)  ? 1.0f : 0.0f;
    const float vD = (i < 23) ? 1.0f : 0.0f;
    const float cU0 = vU * (q0 ? cUe : cUi), cUm = vU * cUi, cU3 = vU * (q5 ? cUe : cUi);
    const float cD0 = vD * (q0 ? cDe : cDi), cDm = vD * cDi, cD3 = vD * (q5 ? cDe : cDi);

    // ---- stencil + weight ----
    float s0 = ct.x + cL0 * lf   + cHi * ct.y + cU0 * up.x + cD0 * dn.x;
    float s1 = ct.y + cL1 * ct.x + cHi * ct.z + cUm * up.y + cDm * dn.y;
    float s2 = ct.z + cHi * ct.y + cR2 * ct.w + cUm * up.z + cDm * dn.z;
    float s3 = ct.w + cHi * ct.z + cR3 * rg   + cU3 * up.w + cD3 * dn.w;

    const float y0 = s0 * wv.x, y1 = s1 * wv.y, y2 = s2 * wv.z, y3 = s3 * wv.w;

    if (STATS) {
        ps1[tid] = (y0 + y1) + (y2 + y3);
        ps2[tid] = (y0 * y0 + y1 * y1) + (y2 * y2 + y3 * y3);
        __syncthreads();
        // stage 1: 32 threads sum 9 consecutive partials each (9*16=144: no
        // group straddles an image boundary)
        if (tid < 32) {
            float a = 0.f, b = 0.f;
            #pragma unroll
            for (int k = 0; k < 9; k++) { a += ps1[tid * 9 + k]; b += ps2[tid * 9 + k]; }
            qs1[tid] = a; qs2[tid] = b;
        }
        __syncthreads();
        // stage 2: 2 threads (one per image) sum 16 group partials
        if (tid < 2) {
            float a = 0.f, b = 0.f;
            #pragma unroll
            for (int k = 0; k < 16; k++) { a += qs1[tid * 16 + k]; b += qs2[tid * 16 + k]; }
            const int bc = blockIdx.x * 2 + tid;
            const int bb = bc >> 9, cc = bc & (C_ - 1);
            g_psum[cc * B_ + bb] = a;
            g_psq [cc * B_ + bb] = b;
        }
    } else {
        const float sc = g_scale[c], sh = g_shift[c];
        float n0 = fmaf(y0, sc, sh), n1 = fmaf(y1, sc, sh);
        float n2 = fmaf(y2, sc, sh), n3 = fmaf(y3, sc, sh);
        n0 = (n0 >= 0.f) ? n0 : SLOPE * n0;
        n1 = (n1 >= 0.f) ? n1 : SLOPE * n1;
        n2 = (n2 >= 0.f) ? n2 : SLOPE * n2;
        n3 = (n3 >= 0.f) ? n3 : SLOPE * n3;
        *(float4*)(out + off) = make_float4(n0, n1, n2, n3);
    }
}

__global__ void k_finalize(const float* __restrict__ gamma,
                           const float* __restrict__ beta) {
    const int c = threadIdx.x;   // 512 threads
    float s1 = 0.0f, s2 = 0.0f;
    #pragma unroll 8
    for (int b = 0; b < B_; b++) {
        s1 += g_psum[c * B_ + b];
        s2 += g_psq [c * B_ + b];
    }
    const float invn = 1.0f / (float)(B_ * NN);
    const float mean = s1 * invn;
    const float var  = s2 * invn - mean * mean;
    const float sc = gamma[c] * rsqrtf(var + BN_EPS);
    g_scale[c] = sc;
    g_shift[c] = beta[c] - mean * sc;
}

extern "C" void kernel_launch(void* const* d_in, const int* in_sizes, int n_in,
                              void* d_out, int out_size) {
    const float* x     = (const float*)d_in[0];   // [64,512,24,24]
    // d_in[1] = adj (unused: grid structure exploited analytically)
    const float* w     = (const float*)d_in[2];   // [512,576]
    const float* gamma = (const float*)d_in[3];   // [512]
    const float* beta  = (const float*)d_in[4];   // [512]
    float* out = (float*)d_out;

    const int nblk = (B_ * C_) / 2;               // 16384 blocks, 2 images each
    k_main<true ><<<nblk, TPB>>>(x, w, out);
    k_finalize<<<1, C_>>>(gamma, beta);
    k_main<false><<<nblk, TPB>>>(x, w, out);
}